// round 9
// baseline (speedup 1.0000x reference)
#include <cuda_runtime.h>
#include <math.h>

// Problem constants: NS = NT = 80, D = 512, N = 6400, kdiag = 79*79 = 6241.
#define NSd   80
#define Dd    512
#define Nn    6400
#define GPERS 148   // persistent grid = #SMs; launch_bounds(256,2) guarantees residency

// ---------------- device scratch (no allocation allowed) ----------------
__device__ float g_e1[NSd * Dd];
__device__ float g_e2[NSd * Dd];
__device__ float g_m1[NSd * Dd];
__device__ float g_m2[NSd * Dd];
__device__ float g_x1[NSd * Dd];
__device__ float g_x2[NSd * Dd];
__device__ float g_y1[NSd * Dd];
__device__ float g_y2[NSd * Dd];
__device__ float g_Mp0[NSd * NSd];
__device__ float g_v[Nn];           // v[p] = Mp[p%80, p/80]
__device__ float g_inv[64 * 64];    // invL of current diag block
__device__ int   g_cnt;             // grid barrier arrival counter
__device__ int   g_gen;             // grid barrier generation

__device__ __forceinline__ float warp_sum(float s) {
#pragma unroll
    for (int o = 16; o > 0; o >>= 1) s += __shfl_xor_sync(0xffffffffu, s, o);
    return s;
}

// ---------------- phase 1: small embedding chain (~25us total) ----------------

__global__ void k_transpose(const float* __restrict__ us, const float* __restrict__ ut) {
    int idx = blockIdx.x * blockDim.x + threadIdx.x;
    if (idx < NSd * Dd) {
        int i = idx >> 9, d = idx & 511;
        g_e1[idx] = us[d * NSd + i];
        g_e2[idx] = ut[d * NSd + i];
    }
}

__global__ void k_mp0(const float* __restrict__ iou) {
    int i = blockIdx.x;
    int warp = threadIdx.x >> 5, lane = threadIdx.x & 31;
    const float* a = g_e1 + i * Dd;
    for (int j = warp; j < NSd; j += 4) {
        const float* b = g_e2 + j * Dd;
        float s = 0.f;
#pragma unroll 4
        for (int d = lane; d < Dd; d += 32) s += a[d] * b[d];
        s = warp_sum(s);
        if (lane == 0) g_Mp0[i * NSd + j] = s + iou[i * NSd + j];
    }
}

__global__ void k_m1m2() {
    int r = blockIdx.x, which = blockIdx.y;
    __shared__ float w[NSd];
    int tid = threadIdx.x;
    if (tid < NSd) w[tid] = (which == 0) ? g_Mp0[r * NSd + tid] : g_Mp0[tid * NSd + r];
    __syncthreads();
    const float* E = (which == 0) ? g_e2 : g_e1;
    float* out     = (which == 0) ? g_m1 : g_m2;
    float acc = 0.f;
#pragma unroll 8
    for (int t = 0; t < NSd; t++) acc += w[t] * E[t * Dd + tid];
    out[r * Dd + tid] = acc;
}

__global__ void k_lamprep() {
    int r = blockIdx.x, which = blockIdx.y;
    const float* e = ((which == 0) ? g_e1 : g_e2) + r * Dd;
    const float* m = ((which == 0) ? g_m1 : g_m2) + r * Dd;
    float* x       = ((which == 0) ? g_x1 : g_x2) + r * Dd;
    float se = 0.f, sm = 0.f;
    for (int d = threadIdx.x; d < Dd; d += 256) {
        float ev = e[d], mv = m[d];
        se += ev * ev; sm += mv * mv;
    }
    se = warp_sum(se); sm = warp_sum(sm);
    __shared__ float rs[8], rm[8], lamS;
    int warp = threadIdx.x >> 5, lane = threadIdx.x & 31;
    if (lane == 0) { rs[warp] = se; rm[warp] = sm; }
    __syncthreads();
    if (threadIdx.x == 0) {
        float SE = 0.f, SM = 0.f;
        for (int t = 0; t < 8; t++) { SE += rs[t]; SM += rm[t]; }
        lamS = sqrtf(SE) / sqrtf(SM);
    }
    __syncthreads();
    float lam = lamS;
    for (int d = threadIdx.x; d < Dd; d += 256) x[d] = e[d] + lam * m[d];
}

__global__ void k_gemmW(const float* __restrict__ W, const float* __restrict__ b) {
    int i = blockIdx.x, which = blockIdx.y;
    const float* X = ((which == 0) ? g_x1 : g_x2) + i * Dd;
    float* Y       = ((which == 0) ? g_y1 : g_y2) + i * Dd;
    __shared__ float xs[Dd];
    for (int d = threadIdx.x; d < Dd; d += 128) xs[d] = X[d];
    __syncthreads();
    int warp = threadIdx.x >> 5, lane = threadIdx.x & 31;
    for (int o = warp; o < Dd; o += 4) {
        const float* wr = W + o * Dd;
        float s = 0.f;
#pragma unroll 4
        for (int d = lane; d < Dd; d += 32) s += xs[d] * wr[d];
        s = warp_sum(s);
        if (lane == 0) Y[o] = fmaxf(s + b[o], 0.f);
    }
}

__global__ void k_norm() {
    int r = blockIdx.x, which = blockIdx.y;
    float* y = ((which == 0) ? g_y1 : g_y2) + r * Dd;
    float s = 0.f;
    for (int d = threadIdx.x; d < Dd; d += 256) { float v = y[d]; s += v * v; }
    s = warp_sum(s);
    __shared__ float rs[8]; __shared__ float invS;
    int warp = threadIdx.x >> 5, lane = threadIdx.x & 31;
    if (lane == 0) rs[warp] = s;
    __syncthreads();
    if (threadIdx.x == 0) {
        float S = 0.f;
        for (int t = 0; t < 8; t++) S += rs[t];
        invS = 1.0f / fmaxf(sqrtf(S), 1e-12f);
    }
    __syncthreads();
    float inv = invS;
    for (int d = threadIdx.x; d < Dd; d += 256) y[d] *= inv;
}

__global__ void k_mp_thr(float* __restrict__ Mp_out, float* __restrict__ flag_out,
                         const float* __restrict__ kf, const float* __restrict__ iou,
                         const float* __restrict__ thrp) {
    int i = blockIdx.x;
    int warp = threadIdx.x >> 5, lane = threadIdx.x & 31;
    const float* a = g_y1 + i * Dd;
    float th = thrp[0];
    for (int j = warp; j < NSd; j += 4) {
        const float* b = g_y2 + j * Dd;
        float s = 0.f;
#pragma unroll 4
        for (int d = lane; d < Dd; d += 32) s += a[d] * b[d];
        s = warp_sum(s);
        if (lane == 0) {
            Mp_out[i * NSd + j] = s;
            g_v[j * NSd + i] = s;
            float fl = (kf[i * NSd + j] == -1.0f || iou[i * NSd + j] == 0.0f || s < th) ? 1.0f : 0.0f;
            flag_out[i * NSd + j] = fl;
        }
    }
}

// ---------------- phase 2: build A into the L output region; reset barrier ----------------
__global__ void k_buildA(float* __restrict__ L) {
    if (blockIdx.x == 0 && threadIdx.x == 0) { g_cnt = 0; g_gen = 0; }
    int p = blockIdx.x;
    int s1 = p % NSd, t1 = p / NSd;
    float vp = g_v[p];
    float* row = L + (size_t)p * Nn;
    for (int q = threadIdx.x; q < Nn; q += 256) {
        float val = 0.f;
        if (q == p) val = 6241.0f;
        else if (q < p) {
            int s2 = q % NSd, t2 = q / NSd;
            if (s1 != s2 && t1 != t2) val = -0.5f * (vp + g_v[q]);
        }
        row[q] = val;
    }
}

// ---------------- phase 3: persistent-kernel blocked Cholesky (NB=64) ----------------

__device__ __forceinline__ void grid_sync() {
    __threadfence();
    __syncthreads();
    if (threadIdx.x == 0) {
        int gen = atomicAdd(&g_gen, 0);
        if (atomicAdd(&g_cnt, 1) == (int)gridDim.x - 1) {
            g_cnt = 0;
            __threadfence();
            atomicExch(&g_gen, gen + 1);
        } else {
            while (atomicAdd(&g_gen, 0) == gen) { }
        }
    }
    __syncthreads();
}

// Factor 64x64 block at A (ld = Nn) in place (lower); write invL into g_inv.
__device__ void fact64(float* __restrict__ A, float* __restrict__ sbuf) {
    float* Lsh    = sbuf;            // 64*65
    float* colbuf = sbuf + 64 * 65;  // 64
    int tid = threadIdx.x;

    for (int idx = tid; idx < 64 * 64; idx += 256) {
        int r = idx >> 6, c = idx & 63;
        if (c <= r) Lsh[r * 65 + c] = A[(size_t)r * Nn + c];
    }
    __syncthreads();

    int tq = tid & 63, trow = tid >> 6;
    for (int c = 0; c < 64; c++) {
        if (tid < 64) colbuf[tid] = Lsh[tid * 65 + c];
        __syncthreads();
        float dv  = sqrtf(colbuf[c]);
        float inv = 1.0f / dv;
        float i2  = inv * inv;
        if (tid < 64) {
            if (tid > c)       Lsh[tid * 65 + c] = colbuf[tid] * inv;
            else if (tid == c) Lsh[c * 65 + c]   = dv;
        }
        if (tq > c) {
            float xq = colbuf[tq] * i2;
            for (int rr = c + 1 + trow; rr < 64; rr += 4)
                Lsh[rr * 65 + tq] -= colbuf[rr] * xq;
        }
        __syncthreads();
    }

    for (int idx = tid; idx < 64 * 64; idx += 256) {
        int r = idx >> 6, c = idx & 63;
        if (c <= r) A[(size_t)r * Nn + c] = Lsh[r * 65 + c];
    }

    if (tid < 64) colbuf[tid] = 1.0f / Lsh[tid * 65 + tid];
    __syncthreads();

    if (tid < 64) {
        int c = tid;
        float x[64];
        x[c] = colbuf[c];
        for (int jj = c + 1; jj < 64; jj++) {
            float s0 = 0.f, s1 = 0.f, s2 = 0.f, s3 = 0.f;
            int k = c;
            for (; k + 3 < jj; k += 4) {
                s0 += Lsh[jj * 65 + k + 0] * x[k + 0];
                s1 += Lsh[jj * 65 + k + 1] * x[k + 1];
                s2 += Lsh[jj * 65 + k + 2] * x[k + 2];
                s3 += Lsh[jj * 65 + k + 3] * x[k + 3];
            }
            for (; k < jj; k++) s0 += Lsh[jj * 65 + k] * x[k];
            x[jj] = -((s0 + s1) + (s2 + s3)) * colbuf[jj];
        }
        for (int jj = 0; jj < 64; jj++)
            g_inv[jj * 64 + c] = (jj >= c) ? x[jj] : 0.f;
    }
    __syncthreads();
}

// Panel solve tile: X = B * invL^T for 128 rows at row0 (in place), step offset jp.
// Register-prefetch double buffered.
__device__ void trsm_tile(float* __restrict__ L, int jp, int M, int row0,
                          float* __restrict__ sbuf) {
    float (*As)[132] = (float(*)[132])sbuf;
    float (*Bs)[68]  = (float(*)[68])(sbuf + 16 * 132);
    float* B = L + (size_t)(jp + 64) * Nn + jp;
    int tid = threadIdx.x;
    float acc[4][8];
#pragma unroll
    for (int u = 0; u < 4; u++)
#pragma unroll
        for (int v = 0; v < 8; v++) acc[u][v] = 0.f;

    int ty = tid >> 3, tx = tid & 7;
    int rr = ty * 4, cc = tx * 8;

    int li[2], lk4[2];
#pragma unroll
    for (int rep = 0; rep < 2; rep++) {
        int f4 = tid + rep * 256;
        li[rep]  = f4 >> 2;
        lk4[rep] = (f4 & 3) << 2;
    }
    int ci  = tid >> 2;
    int ck4 = (tid & 3) << 2;

    float4 pa[2], pbv;
#pragma unroll
    for (int rep = 0; rep < 2; rep++) {
        pa[rep] = make_float4(0.f, 0.f, 0.f, 0.f);
        if (row0 + li[rep] < M)
            pa[rep] = *(const float4*)(B + (size_t)(row0 + li[rep]) * Nn + lk4[rep]);
    }
    pbv = *(const float4*)(g_inv + ci * 64 + ck4);

    for (int kk = 0; kk < 64; kk += 16) {
        __syncthreads();
#pragma unroll
        for (int rep = 0; rep < 2; rep++) {
            As[lk4[rep] + 0][li[rep]] = pa[rep].x;
            As[lk4[rep] + 1][li[rep]] = pa[rep].y;
            As[lk4[rep] + 2][li[rep]] = pa[rep].z;
            As[lk4[rep] + 3][li[rep]] = pa[rep].w;
        }
        Bs[ck4 + 0][ci] = pbv.x; Bs[ck4 + 1][ci] = pbv.y;
        Bs[ck4 + 2][ci] = pbv.z; Bs[ck4 + 3][ci] = pbv.w;
        __syncthreads();
        if (kk < 48) {
            int nk = kk + 16;
#pragma unroll
            for (int rep = 0; rep < 2; rep++) {
                pa[rep] = make_float4(0.f, 0.f, 0.f, 0.f);
                if (row0 + li[rep] < M)
                    pa[rep] = *(const float4*)(B + (size_t)(row0 + li[rep]) * Nn + nk + lk4[rep]);
            }
            pbv = *(const float4*)(g_inv + ci * 64 + nk + ck4);
        }
#pragma unroll
        for (int k = 0; k < 16; k++) {
            float a[4], bq[8];
            *(float4*)&a[0]  = *(const float4*)&As[k][rr];
            *(float4*)&bq[0] = *(const float4*)&Bs[k][cc];
            *(float4*)&bq[4] = *(const float4*)&Bs[k][cc + 4];
#pragma unroll
            for (int u = 0; u < 4; u++)
#pragma unroll
                for (int v = 0; v < 8; v++) acc[u][v] += a[u] * bq[v];
        }
    }
    __syncthreads();
#pragma unroll
    for (int u = 0; u < 4; u++) {
        int gr = row0 + rr + u;
        if (gr < M) {
            float* bp = B + (size_t)gr * Nn + cc;
            float4 c0, c1;
            c0.x = acc[u][0]; c0.y = acc[u][1]; c0.z = acc[u][2]; c0.w = acc[u][3];
            c1.x = acc[u][4]; c1.y = acc[u][5]; c1.z = acc[u][6]; c1.w = acc[u][7];
            *(float4*)bp = c0;
            *(float4*)(bp + 4) = c1;
        }
    }
}

// Trailing-update tile: C(128x128 at by,bx) -= P*P^T. Register-prefetch double buffered.
__device__ void syrk_tile(float* __restrict__ L, int j, int M, int bx, int by,
                          float* __restrict__ sbuf) {
    float (*As)[132] = (float(*)[132])sbuf;
    float (*Bs)[132] = (float(*)[132])(sbuf + 16 * 132);
    const float* P = L + (size_t)(j + 64) * Nn + j;
    float* C       = L + (size_t)(j + 64) * Nn + (j + 64);
    int row0 = by * 128, col0 = bx * 128;
    int tid = threadIdx.x;
    float acc[8][8];
#pragma unroll
    for (int u = 0; u < 8; u++)
#pragma unroll
        for (int v = 0; v < 8; v++) acc[u][v] = 0.f;

    int ty = tid >> 4, tx = tid & 15;
    int rr = ty * 8, cc = tx * 8;

    int li[2], lk4[2];
#pragma unroll
    for (int rep = 0; rep < 2; rep++) {
        int f4 = tid + rep * 256;
        li[rep]  = f4 >> 2;
        lk4[rep] = (f4 & 3) << 2;
    }

    float4 pa[2], pb[2];
#pragma unroll
    for (int rep = 0; rep < 2; rep++) {
        pa[rep] = make_float4(0.f, 0.f, 0.f, 0.f);
        pb[rep] = make_float4(0.f, 0.f, 0.f, 0.f);
        if (row0 + li[rep] < M)
            pa[rep] = *(const float4*)(P + (size_t)(row0 + li[rep]) * Nn + lk4[rep]);
        if (col0 + li[rep] < M)
            pb[rep] = *(const float4*)(P + (size_t)(col0 + li[rep]) * Nn + lk4[rep]);
    }

    for (int kk = 0; kk < 64; kk += 16) {
        __syncthreads();
#pragma unroll
        for (int rep = 0; rep < 2; rep++) {
            As[lk4[rep] + 0][li[rep]] = pa[rep].x;
            As[lk4[rep] + 1][li[rep]] = pa[rep].y;
            As[lk4[rep] + 2][li[rep]] = pa[rep].z;
            As[lk4[rep] + 3][li[rep]] = pa[rep].w;
            Bs[lk4[rep] + 0][li[rep]] = pb[rep].x;
            Bs[lk4[rep] + 1][li[rep]] = pb[rep].y;
            Bs[lk4[rep] + 2][li[rep]] = pb[rep].z;
            Bs[lk4[rep] + 3][li[rep]] = pb[rep].w;
        }
        __syncthreads();
        if (kk < 48) {
            int nk = kk + 16;
#pragma unroll
            for (int rep = 0; rep < 2; rep++) {
                pa[rep] = make_float4(0.f, 0.f, 0.f, 0.f);
                pb[rep] = make_float4(0.f, 0.f, 0.f, 0.f);
                if (row0 + li[rep] < M)
                    pa[rep] = *(const float4*)(P + (size_t)(row0 + li[rep]) * Nn + nk + lk4[rep]);
                if (col0 + li[rep] < M)
                    pb[rep] = *(const float4*)(P + (size_t)(col0 + li[rep]) * Nn + nk + lk4[rep]);
            }
        }
#pragma unroll
        for (int k = 0; k < 16; k++) {
            float a[8], bq[8];
            *(float4*)&a[0]  = *(const float4*)&As[k][rr];
            *(float4*)&a[4]  = *(const float4*)&As[k][rr + 4];
            *(float4*)&bq[0] = *(const float4*)&Bs[k][cc];
            *(float4*)&bq[4] = *(const float4*)&Bs[k][cc + 4];
#pragma unroll
            for (int u = 0; u < 8; u++)
#pragma unroll
                for (int v = 0; v < 8; v++) acc[u][v] += a[u] * bq[v];
        }
    }
    __syncthreads();

    if (by > bx) {
#pragma unroll
        for (int u = 0; u < 8; u++) {
            int gr = row0 + rr + u;
            if (gr < M) {
                float* cp = C + (size_t)gr * Nn + col0 + cc;
                float4 c0 = *(float4*)cp;
                float4 c1 = *(float4*)(cp + 4);
                c0.x -= acc[u][0]; c0.y -= acc[u][1]; c0.z -= acc[u][2]; c0.w -= acc[u][3];
                c1.x -= acc[u][4]; c1.y -= acc[u][5]; c1.z -= acc[u][6]; c1.w -= acc[u][7];
                *(float4*)cp = c0;
                *(float4*)(cp + 4) = c1;
            }
        }
    } else {
#pragma unroll
        for (int u = 0; u < 8; u++) {
            int gr = row0 + rr + u;
            if (gr < M) {
#pragma unroll
                for (int v = 0; v < 8; v++) {
                    int gc = col0 + cc + v;
                    if (gc <= gr) C[(size_t)gr * Nn + gc] -= acc[u][v];
                }
            }
        }
    }
}

// map s in [0, ntB) to bulk tile (bx>=1, by>=bx)
__device__ __forceinline__ void bulk_xy(int s, int& bx, int& by) {
    int byp = (int)((sqrtf(8.0f * (float)s + 1.0f) - 1.0f) * 0.5f);
    while ((byp + 1) * (byp + 2) / 2 <= s) byp++;
    while (byp * (byp + 1) / 2 > s) byp--;
    int bxp = s - ((byp * (byp + 1)) >> 1);
    by = byp + 1; bx = bxp + 1;
}

// Persistent blocked Cholesky with overlapped trsm/fact64.
// Phase A(j): col0 syrk tiles (+ fact64(j+64) chained on block 0) + bulkA bulk tiles.
// Phase B(j): trsm(j+64) tiles + remaining bulk tiles (disjoint write sets).
__global__ __launch_bounds__(256, 2) void chol_persist(float* __restrict__ L) {
    __shared__ float sbuf[4224];
    int bid = blockIdx.x;
    int G   = gridDim.x;

    if (bid == 0) fact64(L, sbuf);
    grid_sync();

    {   // bootstrap trsm for j = 0
        int M0  = Nn - 64;
        int nt0 = (M0 + 127) >> 7;
        for (int t = bid; t < nt0; t += G)
            trsm_tile(L, 0, M0, t << 7, sbuf);
    }
    grid_sync();

    for (int j = 0; j + 64 < Nn; j += 64) {
        int M   = Nn - j - 64;
        int nt  = (M + 127) >> 7;
        int ntS = nt * (nt + 1) / 2;
        int ntB = ntS - nt;                       // bulk tiles (bx >= 1)
        int bulkA = ntB < 3 * (G - 1) ? ntB : 3 * (G - 1);

        // ---- Phase A ----
        if (bid == 0) {
            syrk_tile(L, j, M, 0, 0, sbuf);
            __syncthreads();
            fact64(L + (size_t)(j + 64) * Nn + (j + 64), sbuf);
        } else {
            int nA = (nt - 1) + bulkA;
            for (int i = bid - 1; i < nA; i += G - 1) {
                if (i < nt - 1) {
                    syrk_tile(L, j, M, 0, i + 1, sbuf);
                } else {
                    int bx, by;
                    bulk_xy(i - (nt - 1), bx, by);
                    syrk_tile(L, j, M, bx, by, sbuf);
                }
            }
        }
        grid_sync();

        // ---- Phase B: trsm(j+64) + remaining bulk syrk of step j ----
        int jn  = j + 64;
        int Mp  = Nn - jn - 64;
        int ntp = Mp > 0 ? ((Mp + 127) >> 7) : 0;
        int nB  = ntp + (ntB - bulkA);
        for (int i = bid; i < nB; i += G) {
            if (i < ntp) {
                trsm_tile(L, jn, Mp, i << 7, sbuf);
            } else {
                int bx, by;
                bulk_xy(bulkA + (i - ntp), bx, by);
                syrk_tile(L, j, M, bx, by, sbuf);
            }
        }
        grid_sync();
    }
}

// ---------------- launch ----------------
extern "C" void kernel_launch(void* const* d_in, const int* in_sizes, int n_in,
                              void* d_out, int out_size) {
    (void)in_sizes; (void)n_in; (void)out_size;
    const float* U_src = (const float*)d_in[0];
    const float* U_tgt = (const float*)d_in[1];
    const float* kf    = (const float*)d_in[2];
    const float* thrp  = (const float*)d_in[3];
    const float* iou   = (const float*)d_in[4];
    const float* W     = (const float*)d_in[5];
    const float* b     = (const float*)d_in[6];

    float* out      = (float*)d_out;
    float* Mp_out   = out;                       // [80*80]
    float* Lm       = out + NSd * NSd;           // [6400*6400]
    float* flag_out = out + NSd * NSd + Nn * Nn; // [80*80]

    k_transpose<<<(NSd * Dd + 255) / 256, 256>>>(U_src, U_tgt);
    k_mp0<<<NSd, 128>>>(iou);
    k_m1m2<<<dim3(NSd, 2), 512>>>();
    k_lamprep<<<dim3(NSd, 2), 256>>>();
    k_gemmW<<<dim3(NSd, 2), 128>>>(W, b);
    k_norm<<<dim3(NSd, 2), 256>>>();
    k_mp_thr<<<NSd, 128>>>(Mp_out, flag_out, kf, iou, thrp);
    k_buildA<<<Nn, 256>>>(Lm);          // also resets the grid barrier

    chol_persist<<<GPERS, 256>>>(Lm);   // the entire Cholesky, one launch
}